// round 3
// baseline (speedup 1.0000x reference)
#include <cuda_runtime.h>

typedef unsigned long long u64;

#define NA 16
#define NT 256

// smem float offsets
#define OFF_INV 0          // [256][18]
#define OFF_EQ  4608       // [3][256][18]  (reused as Gc[16][512])
#define OFF_X   18432      // [192][3*16]
#define OFF_PC  27648      // [64][192]     (reused as h_s[512][18])
#define OFF_CHI 39936      // [16][65]
#define OFF_R1  40976      // [16][17]
#define OFF_R2  41248      // [16][17]
#define OFF_CS  41520
#define OFF_MU  41536
#define OFF_IS  41552
#define SM_FLOATS 41568
#define SM_BYTES (SM_FLOATS * 4)

__device__ float d_Pf[256 * 192];
__device__ float d_G1f[256 * 512];
__device__ float d_B1f[512];

static __device__ __forceinline__ u64 pk2(float lo, float hi) {
    u64 r; asm("mov.b64 %0, {%1, %2};" : "=l"(r) : "f"(lo), "f"(hi)); return r;
}
static __device__ __forceinline__ void upk2(u64 v, float& lo, float& hi) {
    asm("mov.b64 {%0, %1}, %2;" : "=f"(lo), "=f"(hi) : "l"(v));
}
static __device__ __forceinline__ u64 ffma2(u64 a, u64 b, u64 c) {
    u64 d; asm("fma.rn.f32x2 %0, %1, %2, %3;" : "=l"(d) : "l"(a), "l"(b), "l"(c));
    return d;
}

// ---------- weight folding (tiny, once per launch) ----------
__global__ void prep_fold(const float* __restrict__ gam, const float* __restrict__ W0,
                          const float* __restrict__ W1, const float* __restrict__ W2,
                          const float* __restrict__ wc, const float* __restrict__ wd) {
    int m = blockIdx.x, c = threadIdx.x;
    float v;
    if (c < 64) {
        v = W0[m * 64 + c];
    } else if (c < 128) {
        int u = c - 64; float s = 0.f;
        #pragma unroll 8
        for (int j = 0; j < 64; j++) s += W1[m * 64 + j] * wc[u * 64 + j];
        v = s;
    } else {
        int u = c - 128; float s = 0.f;
        #pragma unroll 8
        for (int j = 0; j < 64; j++) s += W2[m * 64 + j] * wd[u * 64 + j];
        v = s;
    }
    d_Pf[m * 192 + c] = v * gam[m] * 0.0625f;   // gamma * 1/sqrt(M)
}

__global__ void prep_g1(const float* __restrict__ gw1, const float* __restrict__ stdv) {
    int v = blockIdx.x, h = threadIdx.x;
    d_G1f[v * 512 + h] = gw1[v * 512 + h] / stdv[v];
}

__global__ void prep_b1(const float* __restrict__ gw1, const float* __restrict__ gb1,
                        const float* __restrict__ mean, const float* __restrict__ stdv) {
    int h = threadIdx.x;
    float s = gb1[h];
    for (int v = 0; v < 256; v++) s -= (mean[v] / stdv[v]) * gw1[v * 512 + h];
    d_B1f[h] = s;
}

// ---------- fused main kernel ----------
__global__ __launch_bounds__(NT, 1)
void chiral_main(const float* __restrict__ emb,
                 const float* __restrict__ lnw, const float* __restrict__ lnb,
                 const float* __restrict__ gw2, const float* __restrict__ gb2,
                 float* __restrict__ outp) {
    extern __shared__ float sm[];
    const int t = threadIdx.x;
    const int a = t & 15;        // atom within tile
    const int ug = t >> 4;       // 0..15
    const long abase = (long)blockIdx.x * NA;

    // ---- Phase L: load 16x1024 tile, transposed (atom-minor, stride 18) ----
    {
        const float* src = emb + (long)blockIdx.x * (NA * 1024);
        #pragma unroll
        for (int k = 0; k < 16; k++) {
            int c4 = ug + k * 16;
            float4 v = __ldg((const float4*)src + a * 256 + c4);
            int f = c4 * 4;
            if (f < 256) {
                sm[OFF_INV + (f + 0) * 18 + a] = v.x;
                sm[OFF_INV + (f + 1) * 18 + a] = v.y;
                sm[OFF_INV + (f + 2) * 18 + a] = v.z;
                sm[OFF_INV + (f + 3) * 18 + a] = v.w;
            } else {
                float vv[4] = {v.x, v.y, v.z, v.w};
                #pragma unroll
                for (int j = 0; j < 4; j++) {
                    int g = f + j - 256;
                    int m = g / 3, i = g - m * 3;
                    sm[OFF_EQ + i * 4608 + m * 18 + a] = vv[j];
                }
            }
        }
    }
    __syncthreads();

    // ---- Phase R: per-atom rms -> cs = rms^-3 / sqrt(2K*3K) ----
    {
        float s = 0.f;
        for (int m = ug * 16; m < ug * 16 + 16; m++) {
            #pragma unroll
            for (int i = 0; i < 3; i++) {
                float e = sm[OFF_EQ + i * 4608 + m * 18 + a];
                s += e * e;
            }
        }
        sm[OFF_R1 + ug * 17 + a] = s;
    }
    __syncthreads();
    if (t < 16) {
        float tot = 0.f;
        #pragma unroll
        for (int g = 0; g < 16; g++) tot += sm[OFF_R1 + g * 17 + t];
        float r2 = tot * (1.f / 256.f) + 1e-6f;
        float qr = rsqrtf(r2);
        sm[OFF_CS + t] = qr * qr * qr * rsqrtf(24576.0f);  // 1/sqrt(2K*3K)
    }

    // ---- Phase G: eq GEMM [256]->[192] per atom, packed u-pairs via ffma2 ----
    u64 acc[6][3];
    #pragma unroll
    for (int q = 0; q < 6; q++)
        #pragma unroll
        for (int i = 0; i < 3; i++) acc[q][i] = 0ull;

    for (int mc = 0; mc < 4; mc++) {
        __syncthreads();
        {
            const float4* gp = (const float4*)(d_Pf + mc * 64 * 192);
            float4* sp = (float4*)(sm + OFF_PC);
            #pragma unroll
            for (int k = 0; k < 12; k++) sp[t + k * 256] = __ldg(gp + t + k * 256);
        }
        __syncthreads();
        #pragma unroll 2
        for (int m = 0; m < 64; m++) {
            int mm = mc * 64 + m;
            float e0 = sm[OFF_EQ + 0 * 4608 + mm * 18 + a];
            float e1 = sm[OFF_EQ + 1 * 4608 + mm * 18 + a];
            float e2 = sm[OFF_EQ + 2 * 4608 + mm * 18 + a];
            u64 E0 = pk2(e0, e0), E1 = pk2(e1, e1), E2 = pk2(e2, e2);
            const u64* wr = (const u64*)(sm + OFF_PC + m * 192 + ug * 12);
            #pragma unroll
            for (int q = 0; q < 6; q++) {
                u64 w = wr[q];
                acc[q][0] = ffma2(w, E0, acc[q][0]);
                acc[q][1] = ffma2(w, E1, acc[q][1]);
                acc[q][2] = ffma2(w, E2, acc[q][2]);
            }
        }
    }
    #pragma unroll
    for (int q = 0; q < 6; q++) {
        int u0 = ug * 12 + 2 * q;
        #pragma unroll
        for (int i = 0; i < 3; i++) {
            float lo, hi; upk2(acc[q][i], lo, hi);
            sm[OFF_X + u0 * 48 + i * 16 + a] = lo;
            sm[OFF_X + (u0 + 1) * 48 + i * 16 + a] = hi;
        }
    }
    __syncthreads();

    // ---- Phase C: chi = cs * det(x0,y1,y2); LayerNorm stats ----
    {
        float ps = 0.f, pq = 0.f;
        float csa = sm[OFF_CS + a];
        const float* X = sm + OFF_X;
        #pragma unroll
        for (int q = 0; q < 4; q++) {
            int u = ug * 4 + q;
            float ax = X[u * 48 + a],          ay = X[u * 48 + 16 + a],          az = X[u * 48 + 32 + a];
            float bx = X[(u + 64) * 48 + a],   by = X[(u + 64) * 48 + 16 + a],   bz = X[(u + 64) * 48 + 32 + a];
            float cx = X[(u + 128) * 48 + a],  cy = X[(u + 128) * 48 + 16 + a],  cz = X[(u + 128) * 48 + 32 + a];
            float dx = by * cz - bz * cy;
            float dy = bz * cx - bx * cz;
            float dz = bx * cy - by * cx;
            float chi = csa * (ax * dx + ay * dy + az * dz);
            sm[OFF_CHI + a * 65 + u] = chi;
            ps += chi; pq += chi * chi;
        }
        sm[OFF_R1 + ug * 17 + a] = ps;
        sm[OFF_R2 + ug * 17 + a] = pq;
    }
    __syncthreads();
    if (t < 16) {
        float s = 0.f, sq = 0.f;
        #pragma unroll
        for (int g = 0; g < 16; g++) { s += sm[OFF_R1 + g * 17 + t]; sq += sm[OFF_R2 + g * 17 + t]; }
        float mu = s * (1.f / 64.f);
        float var = fmaxf(sq * (1.f / 64.f) - mu * mu, 0.f);
        sm[OFF_MU + t] = mu;
        sm[OFF_IS + t] = rsqrtf(var + 1e-5f);
    }

    // ---- Phase H: gate layer1 (256 -> 512) + SiLU ----
    u64 hacc[16];
    #pragma unroll
    for (int q = 0; q < 16; q++) hacc[q] = 0ull;

    for (int vc = 0; vc < 16; vc++) {
        __syncthreads();
        {
            const float4* gg = (const float4*)(d_G1f + vc * 8192);
            float4* sg = (float4*)(sm + OFF_EQ);   // Gc chunk in dead eq region
            #pragma unroll
            for (int k = 0; k < 8; k++) sg[t + k * 256] = __ldg(gg + t + k * 256);
        }
        __syncthreads();
        #pragma unroll 2
        for (int vv = 0; vv < 16; vv++) {
            float e = sm[OFF_INV + (vc * 16 + vv) * 18 + a];
            u64 E = pk2(e, e);
            const u64* wr = (const u64*)(sm + OFF_EQ + vv * 512 + ug * 32);
            #pragma unroll
            for (int q = 0; q < 16; q++) hacc[q] = ffma2(wr[q], E, hacc[q]);
        }
    }
    #pragma unroll
    for (int q = 0; q < 16; q++) {
        int h0 = ug * 32 + 2 * q;
        float l0, l1; upk2(hacc[q], l0, l1);
        l0 += __ldg(&d_B1f[h0]);
        l1 += __ldg(&d_B1f[h0 + 1]);
        sm[OFF_PC + h0 * 18 + a]       = l0 / (1.f + __expf(-l0));   // SiLU
        sm[OFF_PC + (h0 + 1) * 18 + a] = l1 / (1.f + __expf(-l1));
    }
    __syncthreads();

    // ---- Phase O: gate layer2 (512 -> 64), sigmoid, LN apply, write out ----
    {
        int ap = t & 7, kg = t >> 3;          // atom-pair, k-pair group
        int k0 = 2 * kg;
        u64 o0 = 0ull, o1 = 0ull;
        #pragma unroll 4
        for (int h = 0; h < 512; h++) {
            u64 w = __ldg((const u64*)(gw2 + h * 64 + k0));
            float s0, s1; upk2(*(const u64*)(sm + OFF_PC + h * 18 + 2 * ap), s0, s1);
            o0 = ffma2(w, pk2(s0, s0), o0);
            o1 = ffma2(w, pk2(s1, s1), o1);
        }
        float b0 = __ldg(gb2 + k0), b1 = __ldg(gb2 + k0 + 1);
        float w0 = __ldg(lnw + k0), w1 = __ldg(lnw + k0 + 1);
        float c0b = __ldg(lnb + k0), c1b = __ldg(lnb + k0 + 1);
        #pragma unroll
        for (int s = 0; s < 2; s++) {
            int aa = 2 * ap + s;
            float l0, l1; upk2(s == 0 ? o0 : o1, l0, l1);
            l0 += b0; l1 += b1;
            float g0 = 1.f / (1.f + __expf(-l0));
            float g1 = 1.f / (1.f + __expf(-l1));
            float mu = sm[OFF_MU + aa], is = sm[OFF_IS + aa];
            float n0 = (sm[OFF_CHI + aa * 65 + k0]     - mu) * is * w0 + c0b;
            float n1 = (sm[OFF_CHI + aa * 65 + k0 + 1] - mu) * is * w1 + c1b;
            *(float2*)(outp + (abase + aa) * 64 + k0) = make_float2(g0 * n0, g1 * n1);
        }
    }
}

extern "C" void kernel_launch(void* const* d_in, const int* in_sizes, int n_in,
                              void* d_out, int out_size) {
    const float* emb  = (const float*)d_in[0];
    const float* mean = (const float*)d_in[1];
    const float* stdv = (const float*)d_in[2];
    const float* gam  = (const float*)d_in[3];
    const float* W0   = (const float*)d_in[4];
    const float* W1   = (const float*)d_in[5];
    const float* W2   = (const float*)d_in[6];
    const float* wc   = (const float*)d_in[7];
    const float* wd   = (const float*)d_in[8];
    const float* lnw  = (const float*)d_in[9];
    const float* lnb  = (const float*)d_in[10];
    const float* gw1  = (const float*)d_in[11];
    const float* gb1  = (const float*)d_in[12];
    const float* gw2  = (const float*)d_in[13];
    const float* gb2  = (const float*)d_in[14];
    float* out = (float*)d_out;

    prep_fold<<<256, 192>>>(gam, W0, W1, W2, wc, wd);
    prep_g1<<<256, 512>>>(gw1, stdv);
    prep_b1<<<1, 512>>>(gw1, gb1, mean, stdv);

    cudaFuncSetAttribute(chiral_main, cudaFuncAttributeMaxDynamicSharedMemorySize, SM_BYTES);
    chiral_main<<<131072 / NA, NT, SM_BYTES>>>(emb, lnw, lnb, gw2, gb2, out);
}

// round 4
// speedup vs baseline: 1.5597x; 1.5597x over previous
#include <cuda_runtime.h>

typedef unsigned long long u64;

#define NT 256
#define NA 16

// smem float offsets (total 104.8 KB -> 2 CTAs/SM)
#define OFF_INV 0            // [256][18]
#define OFF_EQ  4608         // [3][256][18] ; reused: X[192][48], then h_s[512][18]
#define OFF_X   OFF_EQ
#define OFF_H   OFF_EQ
#define OFF_PC  18432        // 6144 f weight-chunk buffer
#define OFF_CHI 24576        // [16][65]
#define OFF_R1  25616        // [16][17]
#define OFF_R2  25888        // [16][17]
#define OFF_CS  26160
#define OFF_MU  26176
#define OFF_IS  26192
#define SM_FLOATS 26208
#define SM_BYTES (SM_FLOATS * 4)

__device__ float d_Pf[256 * 192];
__device__ float d_G1f[256 * 512];
__device__ float d_B1f[512];

static __device__ __forceinline__ u64 pk2(float lo, float hi) {
    u64 r; asm("mov.b64 %0, {%1, %2};" : "=l"(r) : "f"(lo), "f"(hi)); return r;
}
static __device__ __forceinline__ void upk2(u64 v, float& lo, float& hi) {
    asm("mov.b64 {%0, %1}, %2;" : "=f"(lo), "=f"(hi) : "l"(v));
}
static __device__ __forceinline__ u64 ffma2(u64 a, u64 b, u64 c) {
    u64 d; asm("fma.rn.f32x2 %0, %1, %2, %3;" : "=l"(d) : "l"(a), "l"(b), "l"(c));
    return d;
}

// ---------- weight folding (tiny, once per launch) ----------
__global__ void prep_fold(const float* __restrict__ gam, const float* __restrict__ W0,
                          const float* __restrict__ W1, const float* __restrict__ W2,
                          const float* __restrict__ wc, const float* __restrict__ wd) {
    int m = blockIdx.x, c = threadIdx.x;
    float v;
    if (c < 64) {
        v = W0[m * 64 + c];
    } else if (c < 128) {
        int u = c - 64; float s = 0.f;
        #pragma unroll 8
        for (int j = 0; j < 64; j++) s += W1[m * 64 + j] * wc[u * 64 + j];
        v = s;
    } else {
        int u = c - 128; float s = 0.f;
        #pragma unroll 8
        for (int j = 0; j < 64; j++) s += W2[m * 64 + j] * wd[u * 64 + j];
        v = s;
    }
    d_Pf[m * 192 + c] = v * gam[m] * 0.0625f;   // gamma * 1/sqrt(M)
}

__global__ void prep_g1(const float* __restrict__ gw1, const float* __restrict__ stdv) {
    int v = blockIdx.x, h = threadIdx.x;
    d_G1f[v * 512 + h] = gw1[v * 512 + h] / stdv[v];
}

__global__ void prep_b1(const float* __restrict__ gw1, const float* __restrict__ gb1,
                        const float* __restrict__ mean, const float* __restrict__ stdv) {
    int h = threadIdx.x;
    float s = gb1[h];
    for (int v = 0; v < 256; v++) s -= (mean[v] / stdv[v]) * gw1[v * 512 + h];
    d_B1f[h] = s;
}

// ---------- fused main kernel ----------
__global__ __launch_bounds__(NT, 2)
void chiral_main(const float* __restrict__ emb,
                 const float* __restrict__ lnw, const float* __restrict__ lnb,
                 const float* __restrict__ gw2, const float* __restrict__ gb2,
                 float* __restrict__ outp) {
    extern __shared__ float sm[];
    const int t = threadIdx.x;
    const long abase = (long)blockIdx.x * NA;

    // ---- Phase L: load 16x1024 tile (coalesced), transposed stores ----
    {
        const float* src = emb + abase * 1024;
        #pragma unroll
        for (int k = 0; k < 16; k++) {           // k = atom, t = float4 col
            float4 v = __ldg((const float4*)src + k * 256 + t);
            int f = t * 4;
            if (f < 256) {
                sm[OFF_INV + (f + 0) * 18 + k] = v.x;
                sm[OFF_INV + (f + 1) * 18 + k] = v.y;
                sm[OFF_INV + (f + 2) * 18 + k] = v.z;
                sm[OFF_INV + (f + 3) * 18 + k] = v.w;
            } else {
                float vv[4] = {v.x, v.y, v.z, v.w};
                #pragma unroll
                for (int j = 0; j < 4; j++) {
                    int g = f + j - 256;
                    int m = g / 3, i = g - m * 3;
                    sm[OFF_EQ + i * 4608 + m * 18 + k] = vv[j];
                }
            }
        }
    }
    __syncthreads();

    // ---- Phase R: per-atom rms -> cs = rms^-3 / sqrt(2K*3K) ----
    {
        const int a = t & 15, ug = t >> 4;
        float s = 0.f;
        for (int m = ug * 16; m < ug * 16 + 16; m++) {
            #pragma unroll
            for (int i = 0; i < 3; i++) {
                float e = sm[OFF_EQ + i * 4608 + m * 18 + a];
                s += e * e;
            }
        }
        __syncthreads();   // R1 region free
        sm[OFF_R1 + ug * 17 + a] = s;
    }
    __syncthreads();
    if (t < 16) {
        float tot = 0.f;
        #pragma unroll
        for (int g = 0; g < 16; g++) tot += sm[OFF_R1 + g * 17 + t];
        float r2 = tot * (1.f / 256.f) + 1e-6f;
        float qr = rsqrtf(r2);
        sm[OFF_CS + t] = qr * qr * qr * rsqrtf(24576.0f);  // 1/sqrt(2K*3K)
    }

    // ---- Phase G: eq GEMM [256]->[192]; 2 atoms (packed) x 6 u per thread ----
    const int ap  = t & 7;    // atom pair {2ap, 2ap+1}
    const int ug2 = t >> 3;   // 0..31 -> u block ug2*6
    u64 acc[6][3];
    #pragma unroll
    for (int j = 0; j < 6; j++)
        #pragma unroll
        for (int i = 0; i < 3; i++) acc[j][i] = 0ull;

    for (int mc = 0; mc < 8; mc++) {
        __syncthreads();
        {   // stage 32 m-rows of Pf: 6144 floats
            const float4* gp = (const float4*)(d_Pf + mc * 32 * 192);
            float4* sp = (float4*)(sm + OFF_PC);
            #pragma unroll
            for (int k = 0; k < 6; k++) sp[t + k * 256] = __ldg(gp + t + k * 256);
        }
        __syncthreads();
        #pragma unroll 2
        for (int m = 0; m < 32; m++) {
            int mm = mc * 32 + m;
            u64 E0 = *(const u64*)(sm + OFF_EQ + 0 * 4608 + mm * 18 + 2 * ap);
            u64 E1 = *(const u64*)(sm + OFF_EQ + 1 * 4608 + mm * 18 + 2 * ap);
            u64 E2 = *(const u64*)(sm + OFF_EQ + 2 * 4608 + mm * 18 + 2 * ap);
            const u64* wr = (const u64*)(sm + OFF_PC + m * 192 + ug2 * 6);
            #pragma unroll
            for (int j = 0; j < 3; j++) {
                float wl, wh; upk2(wr[j], wl, wh);
                u64 WL = pk2(wl, wl), WH = pk2(wh, wh);
                acc[2*j  ][0] = ffma2(E0, WL, acc[2*j  ][0]);
                acc[2*j  ][1] = ffma2(E1, WL, acc[2*j  ][1]);
                acc[2*j  ][2] = ffma2(E2, WL, acc[2*j  ][2]);
                acc[2*j+1][0] = ffma2(E0, WH, acc[2*j+1][0]);
                acc[2*j+1][1] = ffma2(E1, WH, acc[2*j+1][1]);
                acc[2*j+1][2] = ffma2(E2, WH, acc[2*j+1][2]);
            }
        }
    }
    __syncthreads();   // eq fully consumed; X may overwrite it
    #pragma unroll
    for (int j = 0; j < 6; j++) {
        int u = ug2 * 6 + j;
        #pragma unroll
        for (int i = 0; i < 3; i++)
            *(u64*)(sm + OFF_X + u * 48 + i * 16 + 2 * ap) = acc[j][i];
    }
    __syncthreads();

    // ---- Phase C: chi = cs * det(x0,y1,y2); LN stats ----
    {
        const int a = t & 15, ug = t >> 4;
        float ps = 0.f, pq = 0.f;
        float csa = sm[OFF_CS + a];
        const float* X = sm + OFF_X;
        #pragma unroll
        for (int q = 0; q < 4; q++) {
            int u = ug * 4 + q;
            float ax = X[u * 48 + a],         ay = X[u * 48 + 16 + a],         az = X[u * 48 + 32 + a];
            float bx = X[(u + 64) * 48 + a],  by = X[(u + 64) * 48 + 16 + a],  bz = X[(u + 64) * 48 + 32 + a];
            float cx = X[(u + 128) * 48 + a], cy = X[(u + 128) * 48 + 16 + a], cz = X[(u + 128) * 48 + 32 + a];
            float dx = by * cz - bz * cy;
            float dy = bz * cx - bx * cz;
            float dz = bx * cy - by * cx;
            float chi = csa * (ax * dx + ay * dy + az * dz);
            sm[OFF_CHI + a * 65 + u] = chi;
            ps += chi; pq += chi * chi;
        }
        sm[OFF_R1 + ug * 17 + a] = ps;
        sm[OFF_R2 + ug * 17 + a] = pq;
    }
    __syncthreads();
    if (t < 16) {
        float s = 0.f, sq = 0.f;
        #pragma unroll
        for (int g = 0; g < 16; g++) { s += sm[OFF_R1 + g * 17 + t]; sq += sm[OFF_R2 + g * 17 + t]; }
        float mu = s * (1.f / 64.f);
        float var = fmaxf(sq * (1.f / 64.f) - mu * mu, 0.f);
        sm[OFF_MU + t] = mu;
        sm[OFF_IS + t] = rsqrtf(var + 1e-5f);
    }

    // ---- Phase H: gate layer1 (256->512) + SiLU; 4 atoms x 8 h per thread ----
    const int aq = t & 3;     // atoms 4aq .. 4aq+3
    const int hg = t >> 2;    // 0..63 -> h block hg*8
    u64 hacc[4][4];           // [atom j][h-pair q]
    #pragma unroll
    for (int j = 0; j < 4; j++)
        #pragma unroll
        for (int q = 0; q < 4; q++) hacc[j][q] = 0ull;

    for (int vc = 0; vc < 32; vc++) {
        __syncthreads();
        {   // stage 8 v-rows of G1f: 4096 floats
            const float4* gg = (const float4*)(d_G1f + vc * 8 * 512);
            float4* sg = (float4*)(sm + OFF_PC);
            #pragma unroll
            for (int k = 0; k < 4; k++) sg[t + k * 256] = __ldg(gg + t + k * 256);
        }
        __syncthreads();
        #pragma unroll 2
        for (int vv = 0; vv < 8; vv++) {
            int v = vc * 8 + vv;
            u64 e01 = *(const u64*)(sm + OFF_INV + v * 18 + 4 * aq);
            u64 e23 = *(const u64*)(sm + OFF_INV + v * 18 + 4 * aq + 2);
            float e0, e1, e2, e3;
            upk2(e01, e0, e1); upk2(e23, e2, e3);
            u64 E[4] = {pk2(e0, e0), pk2(e1, e1), pk2(e2, e2), pk2(e3, e3)};
            const u64* wr = (const u64*)(sm + OFF_PC + vv * 512 + hg * 8);
            u64 w0 = wr[0], w1 = wr[1], w2 = wr[2], w3 = wr[3];
            #pragma unroll
            for (int j = 0; j < 4; j++) {
                hacc[j][0] = ffma2(w0, E[j], hacc[j][0]);
                hacc[j][1] = ffma2(w1, E[j], hacc[j][1]);
                hacc[j][2] = ffma2(w2, E[j], hacc[j][2]);
                hacc[j][3] = ffma2(w3, E[j], hacc[j][3]);
            }
        }
    }
    __syncthreads();   // PC free; X dead; h_s may use OFF_H
    #pragma unroll
    for (int q = 0; q < 4; q++) {
        int h0 = hg * 8 + 2 * q;
        float b0 = __ldg(&d_B1f[h0]), b1 = __ldg(&d_B1f[h0 + 1]);
        #pragma unroll
        for (int j = 0; j < 4; j++) {
            float l0, l1; upk2(hacc[j][q], l0, l1);
            l0 += b0; l1 += b1;
            int a = 4 * aq + j;
            sm[OFF_H + h0 * 18 + a]       = l0 / (1.f + __expf(-l0));   // SiLU
            sm[OFF_H + (h0 + 1) * 18 + a] = l1 / (1.f + __expf(-l1));
        }
    }
    __syncthreads();

    // ---- Phase O: gate layer2 (512->64), sigmoid, LN apply, write out ----
    {
        const int kp = t & 31;   // k pair: k0 = 2*kp (coalesced LDG/STG)
        const int ag = t >> 5;   // atoms {2ag, 2ag+1}
        const int k0 = 2 * kp;
        u64 o0 = 0ull, o1 = 0ull;
        #pragma unroll 4
        for (int h = 0; h < 512; h++) {
            u64 w = __ldg((const u64*)(gw2 + h * 64 + k0));
            float s0, s1; upk2(*(const u64*)(sm + OFF_H + h * 18 + 2 * ag), s0, s1);
            o0 = ffma2(w, pk2(s0, s0), o0);
            o1 = ffma2(w, pk2(s1, s1), o1);
        }
        float b0 = __ldg(gb2 + k0), b1 = __ldg(gb2 + k0 + 1);
        float w0 = __ldg(lnw + k0), w1 = __ldg(lnw + k0 + 1);
        float c0b = __ldg(lnb + k0), c1b = __ldg(lnb + k0 + 1);
        #pragma unroll
        for (int s = 0; s < 2; s++) {
            int aa = 2 * ag + s;
            float l0, l1; upk2(s == 0 ? o0 : o1, l0, l1);
            l0 += b0; l1 += b1;
            float g0 = 1.f / (1.f + __expf(-l0));
            float g1 = 1.f / (1.f + __expf(-l1));
            float mu = sm[OFF_MU + aa], is = sm[OFF_IS + aa];
            float n0 = (sm[OFF_CHI + aa * 65 + k0]     - mu) * is * w0 + c0b;
            float n1 = (sm[OFF_CHI + aa * 65 + k0 + 1] - mu) * is * w1 + c1b;
            *(float2*)(outp + (abase + aa) * 64 + k0) = make_float2(g0 * n0, g1 * n1);
        }
    }
}

extern "C" void kernel_launch(void* const* d_in, const int* in_sizes, int n_in,
                              void* d_out, int out_size) {
    const float* emb  = (const float*)d_in[0];
    const float* mean = (const float*)d_in[1];
    const float* stdv = (const float*)d_in[2];
    const float* gam  = (const float*)d_in[3];
    const float* W0   = (const float*)d_in[4];
    const float* W1   = (const float*)d_in[5];
    const float* W2   = (const float*)d_in[6];
    const float* wc   = (const float*)d_in[7];
    const float* wd   = (const float*)d_in[8];
    const float* lnw  = (const float*)d_in[9];
    const float* lnb  = (const float*)d_in[10];
    const float* gw1  = (const float*)d_in[11];
    const float* gb1  = (const float*)d_in[12];
    const float* gw2  = (const float*)d_in[13];
    const float* gb2  = (const float*)d_in[14];
    float* out = (float*)d_out;

    prep_fold<<<256, 192>>>(gam, W0, W1, W2, wc, wd);
    prep_g1<<<256, 512>>>(gw1, stdv);
    prep_b1<<<1, 512>>>(gw1, gb1, mean, stdv);

    cudaFuncSetAttribute(chiral_main, cudaFuncAttributeMaxDynamicSharedMemorySize, SM_BYTES);
    chiral_main<<<131072 / NA, NT, SM_BYTES>>>(emb, lnw, lnb, gw2, gb2, out);
}

// round 5
// speedup vs baseline: 1.5601x; 1.0002x over previous
#include <cuda_runtime.h>

typedef unsigned long long u64;

#define NT 256
#define NA 16

// smem float offsets (total 104.8 KB -> 2 CTAs/SM)
#define OFF_INV 0            // [256][18]
#define OFF_EQ  4608         // [3][256][18] ; reused: X[192][48], then h_s[512][18]
#define OFF_X   OFF_EQ
#define OFF_H   OFF_EQ
#define OFF_PC  18432        // 6144 f weight-chunk buffer
#define OFF_CHI 24576        // [16][65]
#define OFF_R1  25616        // [16][17]
#define OFF_R2  25888        // [16][17]
#define OFF_CS  26160
#define OFF_MU  26176
#define OFF_IS  26192
#define SM_FLOATS 26208
#define SM_BYTES (SM_FLOATS * 4)

__device__ float d_Pf[256 * 192];
__device__ float d_G1f[256 * 512];
__device__ float d_B1f[512];

static __device__ __forceinline__ u64 pk2(float lo, float hi) {
    u64 r; asm("mov.b64 %0, {%1, %2};" : "=l"(r) : "f"(lo), "f"(hi)); return r;
}
static __device__ __forceinline__ void upk2(u64 v, float& lo, float& hi) {
    asm("mov.b64 {%0, %1}, %2;" : "=f"(lo), "=f"(hi) : "l"(v));
}
static __device__ __forceinline__ u64 ffma2(u64 a, u64 b, u64 c) {
    u64 d; asm("fma.rn.f32x2 %0, %1, %2, %3;" : "=l"(d) : "l"(a), "l"(b), "l"(c));
    return d;
}

// ---------- weight folding (tiny, once per launch) ----------
__global__ void prep_fold(const float* __restrict__ gam, const float* __restrict__ W0,
                          const float* __restrict__ W1, const float* __restrict__ W2,
                          const float* __restrict__ wc, const float* __restrict__ wd) {
    int m = blockIdx.x, c = threadIdx.x;
    float v;
    if (c < 64) {
        v = W0[m * 64 + c];
    } else if (c < 128) {
        int u = c - 64; float s = 0.f;
        #pragma unroll 8
        for (int j = 0; j < 64; j++) s += W1[m * 64 + j] * wc[u * 64 + j];
        v = s;
    } else {
        int u = c - 128; float s = 0.f;
        #pragma unroll 8
        for (int j = 0; j < 64; j++) s += W2[m * 64 + j] * wd[u * 64 + j];
        v = s;
    }
    d_Pf[m * 192 + c] = v * gam[m] * 0.0625f;   // gamma * 1/sqrt(M)
}

__global__ void prep_g1(const float* __restrict__ gw1, const float* __restrict__ stdv) {
    int v = blockIdx.x, h = threadIdx.x;
    d_G1f[v * 512 + h] = gw1[v * 512 + h] / stdv[v];
}

__global__ void prep_b1(const float* __restrict__ gw1, const float* __restrict__ gb1,
                        const float* __restrict__ mean, const float* __restrict__ stdv) {
    int h = threadIdx.x;
    float s = gb1[h];
    for (int v = 0; v < 256; v++) s -= (mean[v] / stdv[v]) * gw1[v * 512 + h];
    d_B1f[h] = s;
}

// ---------- fused main kernel ----------
__global__ __launch_bounds__(NT, 2)
void chiral_main(const float* __restrict__ emb,
                 const float* __restrict__ lnw, const float* __restrict__ lnb,
                 const float* __restrict__ gw2, const float* __restrict__ gb2,
                 float* __restrict__ outp) {
    extern __shared__ float sm[];
    const int t = threadIdx.x;
    const long abase = (long)blockIdx.x * NA;

    // ---- Phase L: load 16x1024 tile (coalesced), transposed stores ----
    {
        const float* src = emb + abase * 1024;
        #pragma unroll
        for (int k = 0; k < 16; k++) {           // k = atom, t = float4 col
            float4 v = __ldg((const float4*)src + k * 256 + t);
            int f = t * 4;
            if (f < 256) {
                sm[OFF_INV + (f + 0) * 18 + k] = v.x;
                sm[OFF_INV + (f + 1) * 18 + k] = v.y;
                sm[OFF_INV + (f + 2) * 18 + k] = v.z;
                sm[OFF_INV + (f + 3) * 18 + k] = v.w;
            } else {
                float vv[4] = {v.x, v.y, v.z, v.w};
                #pragma unroll
                for (int j = 0; j < 4; j++) {
                    int g = f + j - 256;
                    int m = g / 3, i = g - m * 3;
                    sm[OFF_EQ + i * 4608 + m * 18 + k] = vv[j];
                }
            }
        }
    }
    __syncthreads();

    // ---- Phase R: per-atom rms -> cs = rms^-3 / sqrt(2K*3K) ----
    {
        const int a = t & 15, ug = t >> 4;
        float s = 0.f;
        for (int m = ug * 16; m < ug * 16 + 16; m++) {
            #pragma unroll
            for (int i = 0; i < 3; i++) {
                float e = sm[OFF_EQ + i * 4608 + m * 18 + a];
                s += e * e;
            }
        }
        __syncthreads();   // R1 region free
        sm[OFF_R1 + ug * 17 + a] = s;
    }
    __syncthreads();
    if (t < 16) {
        float tot = 0.f;
        #pragma unroll
        for (int g = 0; g < 16; g++) tot += sm[OFF_R1 + g * 17 + t];
        float r2 = tot * (1.f / 256.f) + 1e-6f;
        float qr = rsqrtf(r2);
        sm[OFF_CS + t] = qr * qr * qr * rsqrtf(24576.0f);  // 1/sqrt(2K*3K)
    }

    // ---- Phase G: eq GEMM [256]->[192]; 2 atoms (packed) x 6 u per thread ----
    const int ap  = t & 7;    // atom pair {2ap, 2ap+1}
    const int ug2 = t >> 3;   // 0..31 -> u block ug2*6
    u64 acc[6][3];
    #pragma unroll
    for (int j = 0; j < 6; j++)
        #pragma unroll
        for (int i = 0; i < 3; i++) acc[j][i] = 0ull;

    for (int mc = 0; mc < 8; mc++) {
        __syncthreads();
        {   // stage 32 m-rows of Pf: 6144 floats
            const float4* gp = (const float4*)(d_Pf + mc * 32 * 192);
            float4* sp = (float4*)(sm + OFF_PC);
            #pragma unroll
            for (int k = 0; k < 6; k++) sp[t + k * 256] = __ldg(gp + t + k * 256);
        }
        __syncthreads();
        #pragma unroll 2
        for (int m = 0; m < 32; m++) {
            int mm = mc * 32 + m;
            u64 E0 = *(const u64*)(sm + OFF_EQ + 0 * 4608 + mm * 18 + 2 * ap);
            u64 E1 = *(const u64*)(sm + OFF_EQ + 1 * 4608 + mm * 18 + 2 * ap);
            u64 E2 = *(const u64*)(sm + OFF_EQ + 2 * 4608 + mm * 18 + 2 * ap);
            const u64* wr = (const u64*)(sm + OFF_PC + m * 192 + ug2 * 6);
            #pragma unroll
            for (int j = 0; j < 3; j++) {
                float wl, wh; upk2(wr[j], wl, wh);
                u64 WL = pk2(wl, wl), WH = pk2(wh, wh);
                acc[2*j  ][0] = ffma2(E0, WL, acc[2*j  ][0]);
                acc[2*j  ][1] = ffma2(E1, WL, acc[2*j  ][1]);
                acc[2*j  ][2] = ffma2(E2, WL, acc[2*j  ][2]);
                acc[2*j+1][0] = ffma2(E0, WH, acc[2*j+1][0]);
                acc[2*j+1][1] = ffma2(E1, WH, acc[2*j+1][1]);
                acc[2*j+1][2] = ffma2(E2, WH, acc[2*j+1][2]);
            }
        }
    }
    __syncthreads();   // eq fully consumed; X may overwrite it
    #pragma unroll
    for (int j = 0; j < 6; j++) {
        int u = ug2 * 6 + j;
        #pragma unroll
        for (int i = 0; i < 3; i++)
            *(u64*)(sm + OFF_X + u * 48 + i * 16 + 2 * ap) = acc[j][i];
    }
    __syncthreads();

    // ---- Phase C: chi = cs * det(x0,y1,y2); LN stats ----
    {
        const int a = t & 15, ug = t >> 4;
        float ps = 0.f, pq = 0.f;
        float csa = sm[OFF_CS + a];
        const float* X = sm + OFF_X;
        #pragma unroll
        for (int q = 0; q < 4; q++) {
            int u = ug * 4 + q;
            float ax = X[u * 48 + a],         ay = X[u * 48 + 16 + a],         az = X[u * 48 + 32 + a];
            float bx = X[(u + 64) * 48 + a],  by = X[(u + 64) * 48 + 16 + a],  bz = X[(u + 64) * 48 + 32 + a];
            float cx = X[(u + 128) * 48 + a], cy = X[(u + 128) * 48 + 16 + a], cz = X[(u + 128) * 48 + 32 + a];
            float dx = by * cz - bz * cy;
            float dy = bz * cx - bx * cz;
            float dz = bx * cy - by * cx;
            float chi = csa * (ax * dx + ay * dy + az * dz);
            sm[OFF_CHI + a * 65 + u] = chi;
            ps += chi; pq += chi * chi;
        }
        sm[OFF_R1 + ug * 17 + a] = ps;
        sm[OFF_R2 + ug * 17 + a] = pq;
    }
    __syncthreads();
    if (t < 16) {
        float s = 0.f, sq = 0.f;
        #pragma unroll
        for (int g = 0; g < 16; g++) { s += sm[OFF_R1 + g * 17 + t]; sq += sm[OFF_R2 + g * 17 + t]; }
        float mu = s * (1.f / 64.f);
        float var = fmaxf(sq * (1.f / 64.f) - mu * mu, 0.f);
        sm[OFF_MU + t] = mu;
        sm[OFF_IS + t] = rsqrtf(var + 1e-5f);
    }

    // ---- Phase H: gate layer1 (256->512) + SiLU; 4 atoms x 8 h per thread ----
    const int aq = t & 3;     // atoms 4aq .. 4aq+3
    const int hg = t >> 2;    // 0..63 -> h block hg*8
    u64 hacc[4][4];           // [atom j][h-pair q]
    #pragma unroll
    for (int j = 0; j < 4; j++)
        #pragma unroll
        for (int q = 0; q < 4; q++) hacc[j][q] = 0ull;

    for (int vc = 0; vc < 32; vc++) {
        __syncthreads();
        {   // stage 8 v-rows of G1f: 4096 floats
            const float4* gg = (const float4*)(d_G1f + vc * 8 * 512);
            float4* sg = (float4*)(sm + OFF_PC);
            #pragma unroll
            for (int k = 0; k < 4; k++) sg[t + k * 256] = __ldg(gg + t + k * 256);
        }
        __syncthreads();
        #pragma unroll 2
        for (int vv = 0; vv < 8; vv++) {
            int v = vc * 8 + vv;
            u64 e01 = *(const u64*)(sm + OFF_INV + v * 18 + 4 * aq);
            u64 e23 = *(const u64*)(sm + OFF_INV + v * 18 + 4 * aq + 2);
            float e0, e1, e2, e3;
            upk2(e01, e0, e1); upk2(e23, e2, e3);
            u64 E[4] = {pk2(e0, e0), pk2(e1, e1), pk2(e2, e2), pk2(e3, e3)};
            const u64* wr = (const u64*)(sm + OFF_PC + vv * 512 + hg * 8);
            u64 w0 = wr[0], w1 = wr[1], w2 = wr[2], w3 = wr[3];
            #pragma unroll
            for (int j = 0; j < 4; j++) {
                hacc[j][0] = ffma2(w0, E[j], hacc[j][0]);
                hacc[j][1] = ffma2(w1, E[j], hacc[j][1]);
                hacc[j][2] = ffma2(w2, E[j], hacc[j][2]);
                hacc[j][3] = ffma2(w3, E[j], hacc[j][3]);
            }
        }
    }
    __syncthreads();   // PC free; X dead; h_s may use OFF_H
    #pragma unroll
    for (int q = 0; q < 4; q++) {
        int h0 = hg * 8 + 2 * q;
        float b0 = __ldg(&d_B1f[h0]), b1 = __ldg(&d_B1f[h0 + 1]);
        #pragma unroll
        for (int j = 0; j < 4; j++) {
            float l0, l1; upk2(hacc[j][q], l0, l1);
            l0 += b0; l1 += b1;
            int a = 4 * aq + j;
            sm[OFF_H + h0 * 18 + a]       = l0 / (1.f + __expf(-l0));   // SiLU
            sm[OFF_H + (h0 + 1) * 18 + a] = l1 / (1.f + __expf(-l1));
        }
    }
    __syncthreads();

    // ---- Phase O: gate layer2 (512->64), sigmoid, LN apply, write out ----
    {
        const int kp = t & 31;   // k pair: k0 = 2*kp (coalesced LDG/STG)
        const int ag = t >> 5;   // atoms {2ag, 2ag+1}
        const int k0 = 2 * kp;
        u64 o0 = 0ull, o1 = 0ull;
        #pragma unroll 4
        for (int h = 0; h < 512; h++) {
            u64 w = __ldg((const u64*)(gw2 + h * 64 + k0));
            float s0, s1; upk2(*(const u64*)(sm + OFF_H + h * 18 + 2 * ag), s0, s1);
            o0 = ffma2(w, pk2(s0, s0), o0);
            o1 = ffma2(w, pk2(s1, s1), o1);
        }
        float b0 = __ldg(gb2 + k0), b1 = __ldg(gb2 + k0 + 1);
        float w0 = __ldg(lnw + k0), w1 = __ldg(lnw + k0 + 1);
        float c0b = __ldg(lnb + k0), c1b = __ldg(lnb + k0 + 1);
        #pragma unroll
        for (int s = 0; s < 2; s++) {
            int aa = 2 * ag + s;
            float l0, l1; upk2(s == 0 ? o0 : o1, l0, l1);
            l0 += b0; l1 += b1;
            float g0 = 1.f / (1.f + __expf(-l0));
            float g1 = 1.f / (1.f + __expf(-l1));
            float mu = sm[OFF_MU + aa], is = sm[OFF_IS + aa];
            float n0 = (sm[OFF_CHI + aa * 65 + k0]     - mu) * is * w0 + c0b;
            float n1 = (sm[OFF_CHI + aa * 65 + k0 + 1] - mu) * is * w1 + c1b;
            *(float2*)(outp + (abase + aa) * 64 + k0) = make_float2(g0 * n0, g1 * n1);
        }
    }
}

extern "C" void kernel_launch(void* const* d_in, const int* in_sizes, int n_in,
                              void* d_out, int out_size) {
    const float* emb  = (const float*)d_in[0];
    const float* mean = (const float*)d_in[1];
    const float* stdv = (const float*)d_in[2];
    const float* gam  = (const float*)d_in[3];
    const float* W0   = (const float*)d_in[4];
    const float* W1   = (const float*)d_in[5];
    const float* W2   = (const float*)d_in[6];
    const float* wc   = (const float*)d_in[7];
    const float* wd   = (const float*)d_in[8];
    const float* lnw  = (const float*)d_in[9];
    const float* lnb  = (const float*)d_in[10];
    const float* gw1  = (const float*)d_in[11];
    const float* gb1  = (const float*)d_in[12];
    const float* gw2  = (const float*)d_in[13];
    const float* gb2  = (const float*)d_in[14];
    float* out = (float*)d_out;

    prep_fold<<<256, 192>>>(gam, W0, W1, W2, wc, wd);
    prep_g1<<<256, 512>>>(gw1, stdv);
    prep_b1<<<1, 512>>>(gw1, gb1, mean, stdv);

    cudaFuncSetAttribute(chiral_main, cudaFuncAttributeMaxDynamicSharedMemorySize, SM_BYTES);
    chiral_main<<<131072 / NA, NT, SM_BYTES>>>(emb, lnw, lnb, gw2, gb2, out);
}

// round 8
// speedup vs baseline: 2.2679x; 1.4537x over previous
#include <cuda_runtime.h>

typedef unsigned long long u64;
typedef unsigned int u32;
typedef unsigned short u16;

#define NT 256
#define ATOMS 64

// ---------------- smem map (bytes) ----------------
#define SM_X      0          // X[3][64][194] f32, X_i stride 49664
#define X_STR     194
#define SM_INVA   0          // gate alias: [2][64][264hw]
#define INVA_SIDE 33792
#define INVA_STR  264
#define SM_RED    69632      // 49152 B gate2 reduction
#define SM_EQA    148992     // [2][64][40hw]
#define EQA_SIDE  5120
#define SM_B      159232     // up to 34816 B
#define SM_CHI    194048     // 64*66*4
#define CHI_STR   66
#define SM_CS     210944     // 128 f32
#define SM_RSS    211456     // 512 f32
#define SM_BYTES  213504

__device__ u16 d_PfT_h[192 * 256], d_PfT_l[192 * 256];
__device__ u16 d_G1T_h[512 * 256], d_G1T_l[512 * 256];
__device__ u16 d_G2T_h[64 * 512],  d_G2T_l[64 * 512];
__device__ float d_B1f[512];

// ---------------- helpers ----------------
static __device__ __forceinline__ u32 smem_u32(const void* p) {
    u32 a;
    asm("{ .reg .u64 t; cvta.to.shared.u64 t, %1; cvt.u32.u64 %0, t; }" : "=r"(a) : "l"(p));
    return a;
}
static __device__ __forceinline__ void ldsm4(u32* r, u32 addr) {
    asm volatile("ldmatrix.sync.aligned.m8n8.x4.shared.b16 {%0,%1,%2,%3}, [%4];"
        : "=r"(r[0]), "=r"(r[1]), "=r"(r[2]), "=r"(r[3]) : "r"(addr));
}
static __device__ __forceinline__ void ldsm2(u32* r, u32 addr) {
    asm volatile("ldmatrix.sync.aligned.m8n8.x2.shared.b16 {%0,%1}, [%2];"
        : "=r"(r[0]), "=r"(r[1]) : "r"(addr));
}
static __device__ __forceinline__ void mma16816(float* d, const u32* a, const u32* b) {
    asm volatile(
        "mma.sync.aligned.m16n8k16.row.col.f32.bf16.bf16.f32 "
        "{%0,%1,%2,%3},{%4,%5,%6,%7},{%8,%9},{%0,%1,%2,%3};"
        : "+f"(d[0]), "+f"(d[1]), "+f"(d[2]), "+f"(d[3])
        : "r"(a[0]), "r"(a[1]), "r"(a[2]), "r"(a[3]), "r"(b[0]), "r"(b[1]));
}
static __device__ __forceinline__ void split1(float v, u16& h, u16& l) {
    u32 hp;
    asm("cvt.rn.bf16x2.f32 %0, %1, %2;" : "=r"(hp) : "f"(0.f), "f"(v));
    float lr = v - __uint_as_float(hp << 16);
    u32 lp;
    asm("cvt.rn.bf16x2.f32 %0, %1, %2;" : "=r"(lp) : "f"(0.f), "f"(lr));
    h = (u16)hp; l = (u16)lp;
}
// pack pair (a = element k, b = element k+1) into bf16x2 hi + lo
static __device__ __forceinline__ void splitpk(float a, float b, u32& h, u32& l) {
    u32 hp;
    asm("cvt.rn.bf16x2.f32 %0, %1, %2;" : "=r"(hp) : "f"(b), "f"(a));
    float ra = a - __uint_as_float(hp << 16);
    float rb = b - __uint_as_float(hp & 0xFFFF0000u);
    asm("cvt.rn.bf16x2.f32 %0, %1, %2;" : "=r"(l) : "f"(rb), "f"(ra));
    h = hp;
}
static __device__ __forceinline__ float silu(float x) { return x / (1.f + __expf(-x)); }
static __device__ __forceinline__ float sigm(float x) { return 1.f / (1.f + __expf(-x)); }

// ---------------- prep kernels ----------------
__global__ void prep_pf(const float* __restrict__ gam, const float* __restrict__ W0,
                        const float* __restrict__ W1, const float* __restrict__ W2,
                        const float* __restrict__ wc, const float* __restrict__ wd) {
    int n = blockIdx.x, m = threadIdx.x;      // n: 0..191 (role*64+u), m: 0..255
    int role = n >> 6, u = n & 63;
    float v;
    if (role == 0) v = W0[m * 64 + u];
    else {
        const float* Wx = (role == 1) ? W1 : W2;
        const float* wx = (role == 1) ? wc : wd;
        float s = 0.f;
        #pragma unroll 8
        for (int j = 0; j < 64; j++) s += Wx[m * 64 + j] * wx[u * 64 + j];
        v = s;
    }
    v *= gam[m] * 0.0625f;
    u16 h, l; split1(v, h, l);
    d_PfT_h[n * 256 + m] = h; d_PfT_l[n * 256 + m] = l;
}
__global__ void prep_g1(const float* __restrict__ gw1, const float* __restrict__ stdv) {
    int h = blockIdx.x, v = threadIdx.x;
    u16 a, b; split1(gw1[v * 512 + h] / stdv[v], a, b);
    d_G1T_h[h * 256 + v] = a; d_G1T_l[h * 256 + v] = b;
}
__global__ void prep_g2(const float* __restrict__ gw2) {
    int k = blockIdx.x, h = threadIdx.x;
    u16 a, b; split1(gw2[h * 64 + k], a, b);
    d_G2T_h[k * 512 + h] = a; d_G2T_l[k * 512 + h] = b;
}
__global__ void prep_b1(const float* __restrict__ gw1, const float* __restrict__ gb1,
                        const float* __restrict__ mean, const float* __restrict__ stdv) {
    int h = threadIdx.x;
    float s = gb1[h];
    for (int v = 0; v < 256; v++) s -= (mean[v] / stdv[v]) * gw1[v * 512 + h];
    d_B1f[h] = s;
}

// ---------------- fused main kernel ----------------
__global__ __launch_bounds__(NT)
void chiral_tc(const float* __restrict__ emb,
               const float* __restrict__ lnw, const float* __restrict__ lnb,
               const float* __restrict__ gb2, float* __restrict__ outp) {
    extern __shared__ char smc[];
    float* smf = (float*)smc;
    const u32 sb = smem_u32(smc);
    const int tid = threadIdx.x, lane = tid & 31, w = tid >> 5;
    const int l15 = lane & 15;
    const long abase = (long)blockIdx.x * ATOMS;

    // ldmatrix lane address components
    const int arow = (lane & 7) + ((lane >> 3) & 1) * 8;   // A x4 row
    const int akq  = (lane >> 4) * 8;                      // A x4 k sub-offset
    const int brow = l15 & 7;                              // B x2 row
    const int bkq  = ((l15 >> 3) & 1) * 8;                 // B x2 k sub-offset

    const int mw = w >> 2, uw = w & 3;   // eq warp tile: rows mw*32, cols uw*48
    float rloc = 0.f;

    // ============ eq GEMM: 3 sweeps over spatial dim i ============
    for (int i = 0; i < 3; i++) {
        float acc[2][6][4];
        #pragma unroll
        for (int mt = 0; mt < 2; mt++)
            #pragma unroll
            for (int nt = 0; nt < 6; nt++)
                #pragma unroll
                for (int e = 0; e < 4; e++) acc[mt][nt][e] = 0.f;

        for (int kc = 0; kc < 8; kc++) {
            __syncthreads();
            {   // stage A_i chunk [64 atoms][32 m] hi/lo
                int a = tid >> 2, q = tid & 3;
                const float* src = emb + (abase + a) * 1024 + 256 + (kc * 32 + q * 8) * 3 + i;
                #pragma unroll
                for (int j = 0; j < 8; j++) {
                    float f = __ldg(src + j * 3);
                    rloc += f * f;
                    u16 h, l; split1(f, h, l);
                    int m = q * 8 + j;
                    *(u16*)(smc + SM_EQA + (a * 40 + m) * 2) = h;
                    *(u16*)(smc + SM_EQA + EQA_SIDE + (a * 40 + m) * 2) = l;
                }
            }
            {   // stage B chunk [192 n][32 k] hi/lo  (192*16 u32 = 3072)
                #pragma unroll
                for (int rr = 0; rr < 12; rr++) {
                    int idx = tid + rr * 256;
                    int row = idx >> 4, c = idx & 15;
                    *(u32*)(smc + SM_B + row * 80 + c * 4) =
                        *(const u32*)(d_PfT_h + row * 256 + kc * 32 + c * 2);
                    *(u32*)(smc + SM_B + 15360 + row * 80 + c * 4) =
                        *(const u32*)(d_PfT_l + row * 256 + kc * 32 + c * 2);
                }
            }
            __syncthreads();
            #pragma unroll
            for (int ks = 0; ks < 2; ks++) {
                u32 A[2][2][4];
                #pragma unroll
                for (int mt = 0; mt < 2; mt++)
                    #pragma unroll
                    for (int s = 0; s < 2; s++)
                        ldsm4(A[mt][s], sb + SM_EQA + s * EQA_SIDE +
                              2 * ((mw * 32 + mt * 16 + arow) * 40 + ks * 16 + akq));
                #pragma unroll
                for (int nt = 0; nt < 6; nt++) {
                    u32 Bh[2], Bl[2];
                    u32 boff = 2 * ((uw * 48 + nt * 8 + brow) * 40 + ks * 16 + bkq);
                    ldsm2(Bh, sb + SM_B + boff);
                    ldsm2(Bl, sb + SM_B + 15360 + boff);
                    #pragma unroll
                    for (int mt = 0; mt < 2; mt++) {
                        mma16816(acc[mt][nt], A[mt][0], Bh);
                        mma16816(acc[mt][nt], A[mt][1], Bh);
                        mma16816(acc[mt][nt], A[mt][0], Bl);
                    }
                }
            }
        }
        // stash X_i to smem (f32)
        #pragma unroll
        for (int mt = 0; mt < 2; mt++)
            #pragma unroll
            for (int nt = 0; nt < 6; nt++) {
                int r0 = mw * 32 + mt * 16 + (lane >> 2);
                int c0 = uw * 48 + nt * 8 + (lane & 3) * 2;
                float* xp = smf + i * 12416;
                xp[r0 * X_STR + c0]       = acc[mt][nt][0];
                xp[r0 * X_STR + c0 + 1]   = acc[mt][nt][1];
                xp[(r0 + 8) * X_STR + c0]     = acc[mt][nt][2];
                xp[(r0 + 8) * X_STR + c0 + 1] = acc[mt][nt][3];
            }
    }
    __syncthreads();

    // ============ rms -> cs ============
    smf[(SM_RSS >> 2) + tid] = rloc;
    __syncthreads();
    if (tid < 64) {
        const float* rp = smf + (SM_RSS >> 2);
        float s = rp[tid * 4] + rp[tid * 4 + 1] + rp[tid * 4 + 2] + rp[tid * 4 + 3];
        float qr = rsqrtf(s * (1.f / 256.f) + 1e-6f);
        smf[(SM_CS >> 2) + tid] = qr * qr * qr * rsqrtf(24576.0f);
    }
    __syncthreads();

    // ============ chi = cs * det; LN stats ============
    {
        int a = tid >> 2, ug = tid & 3;
        float cs = smf[(SM_CS >> 2) + a];
        float ps = 0.f, pq = 0.f;
        #pragma unroll 4
        for (int uu = 0; uu < 16; uu++) {
            int u = ug * 16 + uu;
            const float* X0 = smf + 0 * 12416 + a * X_STR;
            const float* X1 = smf + 1 * 12416 + a * X_STR;
            const float* X2 = smf + 2 * 12416 + a * X_STR;
            float ax = X0[u],       bx = X0[u + 64],  cx = X0[u + 128];
            float ay = X1[u],       by = X1[u + 64],  cy = X1[u + 128];
            float az = X2[u],       bz = X2[u + 64],  cz = X2[u + 128];
            float det = ax * (by * cz - bz * cy) + ay * (bz * cx - bx * cz)
                      + az * (bx * cy - by * cx);
            float chi = cs * det;
            smf[(SM_CHI >> 2) + a * CHI_STR + u] = chi;
            ps += chi; pq += chi * chi;
        }
        smf[(SM_RSS >> 2) + tid] = ps;
        smf[(SM_RSS >> 2) + 256 + tid] = pq;
    }
    __syncthreads();
    if (tid < 64) {
        const float* rp = smf + (SM_RSS >> 2);
        float s = rp[tid * 4] + rp[tid * 4 + 1] + rp[tid * 4 + 2] + rp[tid * 4 + 3];
        float q = rp[256 + tid * 4] + rp[256 + tid * 4 + 1] + rp[256 + tid * 4 + 2] + rp[256 + tid * 4 + 3];
        float mu = s * (1.f / 64.f);
        float var = fmaxf(q * (1.f / 64.f) - mu * mu, 0.f);
        smf[(SM_CS >> 2) + tid] = mu;
        smf[(SM_CS >> 2) + 64 + tid] = rsqrtf(var + 1e-5f);
    }
    __syncthreads();
    {   // apply LN in-place
        int a = tid >> 2, ug = tid & 3;
        float mu = smf[(SM_CS >> 2) + a], is = smf[(SM_CS >> 2) + 64 + a];
        #pragma unroll 4
        for (int uu = 0; uu < 16; uu++) {
            int u = ug * 16 + uu;
            float c = smf[(SM_CHI >> 2) + a * CHI_STR + u];
            smf[(SM_CHI >> 2) + a * CHI_STR + u] =
                (c - mu) * is * __ldg(lnw + u) + __ldg(lnb + u);
        }
    }
    __syncthreads();   // X region now dead -> gate may reuse

    // ============ gate phase ============
    {   // stage inv A full [64][256] hi/lo
        int a = tid >> 2, q = tid & 3;
        const float4* src = (const float4*)(emb + (abase + a) * 1024 + q * 64);
        #pragma unroll
        for (int j = 0; j < 16; j++) {
            float4 v = __ldg(src + j);
            float vv[4] = {v.x, v.y, v.z, v.w};
            #pragma unroll
            for (int e = 0; e < 4; e++) {
                int k = q * 64 + j * 4 + e;
                u16 h, l; split1(vv[e], h, l);
                *(u16*)(smc + SM_INVA + (a * INVA_STR + k) * 2) = h;
                *(u16*)(smc + SM_INVA + INVA_SIDE + (a * INVA_STR + k) * 2) = l;
            }
        }
    }
    const int gmw = w >> 2, gnw = w & 3;   // rows gmw*32, h-cols gnw*32 (per hc)
    float g2acc[2][8][4];
    #pragma unroll
    for (int mt = 0; mt < 2; mt++)
        #pragma unroll
        for (int nt = 0; nt < 8; nt++)
            #pragma unroll
            for (int e = 0; e < 4; e++) g2acc[mt][nt][e] = 0.f;

    for (int hc = 0; hc < 4; hc++) {
        float g1acc[2][4][4];
        #pragma unroll
        for (int mt = 0; mt < 2; mt++)
            #pragma unroll
            for (int nt = 0; nt < 4; nt++)
                #pragma unroll
                for (int e = 0; e < 4; e++) g1acc[mt][nt][e] = 0.f;

        for (int kc = 0; kc < 8; kc++) {
            __syncthreads();
            {   // stage B1 chunk [128 h][32 k] hi/lo (128*16 u32 = 2048)
                #pragma unroll
                for (int rr = 0; rr < 8; rr++) {
                    int idx = tid + rr * 256;
                    int row = idx >> 4, c = idx & 15;
                    *(u32*)(smc + SM_B + row * 80 + c * 4) =
                        *(const u32*)(d_G1T_h + (hc * 128 + row) * 256 + kc * 32 + c * 2);
                    *(u32*)(smc + SM_B + 10240 + row * 80 + c * 4) =
                        *(const u32*)(d_G1T_l + (hc * 128 + row) * 256 + kc * 32 + c * 2);
                }
            }
            __syncthreads();
            #pragma unroll
            for (int ks = 0; ks < 2; ks++) {
                u32 A[2][2][4];
                #pragma unroll
                for (int mt = 0; mt < 2; mt++)
                    #pragma unroll
                    for (int s = 0; s < 2; s++)
                        ldsm4(A[mt][s], sb + SM_INVA + s * INVA_SIDE +
                              2 * ((gmw * 32 + mt * 16 + arow) * INVA_STR + kc * 32 + ks * 16 + akq));
                #pragma unroll
                for (int nt = 0; nt < 4; nt++) {
                    u32 Bh[2], Bl[2];
                    u32 boff = 2 * ((gnw * 32 + nt * 8 + brow) * 40 + ks * 16 + bkq);
                    ldsm2(Bh, sb + SM_B + boff);
                    ldsm2(Bl, sb + SM_B + 10240 + boff);
                    #pragma unroll
                    for (int mt = 0; mt < 2; mt++) {
                        mma16816(g1acc[mt][nt], A[mt][0], Bh);
                        mma16816(g1acc[mt][nt], A[mt][1], Bh);
                        mma16816(g1acc[mt][nt], A[mt][0], Bl);
                    }
                }
            }
        }
        // SiLU + re-split into gate2 A fragments (in registers)
        u32 a2h[2][2][4], a2l[2][2][4];
        #pragma unroll
        for (int mt = 0; mt < 2; mt++)
            #pragma unroll
            for (int kt = 0; kt < 2; kt++)
                #pragma unroll
                for (int half = 0; half < 2; half++) {
                    int nt = kt * 2 + half;
                    int hb = hc * 128 + gnw * 32 + nt * 8 + (lane & 3) * 2;
                    float b0 = __ldg(d_B1f + hb), b1 = __ldg(d_B1f + hb + 1);
                    float s0 = silu(g1acc[mt][nt][0] + b0);
                    float s1 = silu(g1acc[mt][nt][1] + b1);
                    float s2 = silu(g1acc[mt][nt][2] + b0);
                    float s3 = silu(g1acc[mt][nt][3] + b1);
                    splitpk(s0, s1, a2h[mt][kt][half * 2], a2l[mt][kt][half * 2]);
                    splitpk(s2, s3, a2h[mt][kt][half * 2 + 1], a2l[mt][kt][half * 2 + 1]);
                }
        __syncthreads();
        {   // stage B2 [64 n][128 h-slice] hi/lo (64*64 u32 = 4096)
            #pragma unroll
            for (int rr = 0; rr < 16; rr++) {
                int idx = tid + rr * 256;
                int row = idx >> 6, c = idx & 63;
                *(u32*)(smc + SM_B + row * 272 + c * 4) =
                    *(const u32*)(d_G2T_h + row * 512 + hc * 128 + c * 2);
                *(u32*)(smc + SM_B + 17408 + row * 272 + c * 4) =
                    *(const u32*)(d_G2T_l + row * 512 + hc * 128 + c * 2);
            }
        }
        __syncthreads();
        #pragma unroll
        for (int kt = 0; kt < 2; kt++)
            #pragma unroll
            for (int nt = 0; nt < 8; nt++) {
                u32 Bh[2], Bl[2];
                u32 boff = 2 * ((nt * 8 + brow) * 136 + gnw * 32 + kt * 16 + bkq);
                ldsm2(Bh, sb + SM_B + boff);
                ldsm2(Bl, sb + SM_B + 17408 + boff);
                #pragma unroll
                for (int mt = 0; mt < 2; mt++) {
                    mma16816(g2acc[mt][nt], a2h[mt][kt], Bh);
                    mma16816(g2acc[mt][nt], a2l[mt][kt], Bh);
                    mma16816(g2acc[mt][nt], a2h[mt][kt], Bl);
                }
            }
    }
    // cross-warp reduction over gnw, then epilogue
    __syncthreads();
    if (gnw != 0) {
        float* rp = smf + (SM_RED >> 2) + (((gnw - 1) * 2 + gmw) * 32 + lane) * 64;
        #pragma unroll
        for (int mt = 0; mt < 2; mt++)
            #pragma unroll
            for (int nt = 0; nt < 8; nt++)
                #pragma unroll
                for (int e = 0; e < 4; e++)
                    rp[mt * 32 + nt * 4 + e] = g2acc[mt][nt][e];
    }
    __syncthreads();
    if (gnw == 0) {
        #pragma unroll
        for (int p = 0; p < 3; p++) {
            const float* rp = smf + (SM_RED >> 2) + ((p * 2 + gmw) * 32 + lane) * 64;
            #pragma unroll
            for (int mt = 0; mt < 2; mt++)
                #pragma unroll
                for (int nt = 0; nt < 8; nt++)
                    #pragma unroll
                    for (int e = 0; e < 4; e++)
                        g2acc[mt][nt][e] += rp[mt * 32 + nt * 4 + e];
        }
        #pragma unroll
        for (int mt = 0; mt < 2; mt++)
            #pragma unroll
            for (int nt = 0; nt < 8; nt++) {
                int r0 = gmw * 32 + mt * 16 + (lane >> 2);
                int c0 = nt * 8 + (lane & 3) * 2;
                float b0 = __ldg(gb2 + c0), b1 = __ldg(gb2 + c0 + 1);
                float g0 = sigm(g2acc[mt][nt][0] + b0);
                float g1 = sigm(g2acc[mt][nt][1] + b1);
                float n0 = smf[(SM_CHI >> 2) + r0 * CHI_STR + c0];
                float n1 = smf[(SM_CHI >> 2) + r0 * CHI_STR + c0 + 1];
                *(float2*)(outp + (abase + r0) * 64 + c0) = make_float2(g0 * n0, g1 * n1);
                int r1 = r0 + 8;
                float g2 = sigm(g2acc[mt][nt][2] + b0);
                float g3 = sigm(g2acc[mt][nt][3] + b1);
                float n2 = smf[(SM_CHI >> 2) + r1 * CHI_STR + c0];
                float n3 = smf[(SM_CHI >> 2) + r1 * CHI_STR + c0 + 1];
                *(float2*)(outp + (abase + r1) * 64 + c0) = make_float2(g2 * n2, g3 * n3);
            }
    }
}

extern "C" void kernel_launch(void* const* d_in, const int* in_sizes, int n_in,
                              void* d_out, int out_size) {
    const float* emb  = (const float*)d_in[0];
    const float* mean = (const float*)d_in[1];
    const float* stdv = (const float*)d_in[2];
    const float* gam  = (const float*)d_in[3];
    const float* W0   = (const float*)d_in[4];
    const float* W1   = (const float*)d_in[5];
    const float* W2   = (const float*)d_in[6];
    const float* wc   = (const float*)d_in[7];
    const float* wd   = (const float*)d_in[8];
    const float* lnw  = (const float*)d_in[9];
    const float* lnb  = (const float*)d_in[10];
    const float* gw1  = (const float*)d_in[11];
    const float* gb1  = (const float*)d_in[12];
    const float* gw2  = (const float*)d_in[13];
    const float* gb2  = (const float*)d_in[14];
    float* out = (float*)d_out;

    prep_pf<<<192, 256>>>(gam, W0, W1, W2, wc, wd);
    prep_g1<<<512, 256>>>(gw1, stdv);
    prep_g2<<<64, 512>>>(gw2);
    prep_b1<<<1, 512>>>(gw1, gb1, mean, stdv);

    cudaFuncSetAttribute(chiral_tc, cudaFuncAttributeMaxDynamicSharedMemorySize, SM_BYTES);
    chiral_tc<<<131072 / ATOMS, NT, SM_BYTES>>>(emb, lnw, lnb, gb2, out);
}